// round 8
// baseline (speedup 1.0000x reference)
#include <cuda_runtime.h>
#include <cuda_bf16.h>
#include <cstdint>

#define BATCH 32
#define NDIM  768
#define MTOT  (BATCH * NDIM)     // 24576
#define BK    32
#define NKT   (NDIM / BK)        // 24

typedef __nv_bfloat16 bf16;

__device__ bf16 g_Xhi[(size_t)MTOT * NDIM];
__device__ bf16 g_Xlo[(size_t)MTOT * NDIM];
__device__ bf16 g_Wl_hi[(size_t)NDIM * NDIM];
__device__ bf16 g_Wl_lo[(size_t)NDIM * NDIM];
__device__ bf16 g_Wl1_hi[(size_t)NDIM * NDIM];
__device__ bf16 g_Adj[(size_t)BATCH * NDIM * NDIM];
__device__ bf16 g_Y [(size_t)MTOT * NDIM];          // adj_n @ Xhi

#define APAD 40
#define BPAD 136
#define A_BYTES (128 * APAD * 2)
#define B_BYTES (BK * BPAD * 2)

// 3-term kernel: 2 stages
#define S3_AHI 0
#define S3_ALO (A_BYTES)
#define S3_BHI (2 * A_BYTES)
#define S3_BLO (2 * A_BYTES + B_BYTES)
#define S3_BYTES (2 * A_BYTES + 2 * B_BYTES)   // 37888
#define SMEM3 (2 * S3_BYTES)                   // 75776 -> 2 CTAs/SM

// 1-term kernels: 3 stages
#define S1_AHI 0
#define S1_BHI (A_BYTES)
#define S1_BYTES (A_BYTES + B_BYTES)           // 18944
#define SMEM1T (3 * S1_BYTES)                  // 56832 -> 2 CTAs/SM

__device__ __forceinline__ uint32_t smem_u32(const void* p) {
    uint32_t a;
    asm("{ .reg .u64 t; cvta.to.shared.u64 t, %1; cvt.u32.u64 %0, t; }" : "=r"(a) : "l"(p));
    return a;
}
__device__ __forceinline__ void ldsm4(uint32_t* r, uint32_t addr) {
    asm volatile("ldmatrix.sync.aligned.m8n8.x4.shared.b16 {%0,%1,%2,%3}, [%4];"
                 : "=r"(r[0]), "=r"(r[1]), "=r"(r[2]), "=r"(r[3]) : "r"(addr));
}
__device__ __forceinline__ void ldsm4t(uint32_t* r, uint32_t addr) {
    asm volatile("ldmatrix.sync.aligned.m8n8.x4.trans.shared.b16 {%0,%1,%2,%3}, [%4];"
                 : "=r"(r[0]), "=r"(r[1]), "=r"(r[2]), "=r"(r[3]) : "r"(addr));
}
__device__ __forceinline__ void hmma(float* d, const uint32_t* a, const uint32_t* b) {
    asm volatile("mma.sync.aligned.m16n8k16.row.col.f32.bf16.bf16.f32 "
                 "{%0,%1,%2,%3}, {%4,%5,%6,%7}, {%8,%9}, {%0,%1,%2,%3};"
                 : "+f"(d[0]), "+f"(d[1]), "+f"(d[2]), "+f"(d[3])
                 : "r"(a[0]), "r"(a[1]), "r"(a[2]), "r"(a[3]), "r"(b[0]), "r"(b[1]));
}
__device__ __forceinline__ void cp16(uint32_t dst, const void* src) {
    asm volatile("cp.async.cg.shared.global [%0], [%1], 16;" :: "r"(dst), "l"(src));
}
#define CP_COMMIT() asm volatile("cp.async.commit_group;" ::: "memory")
#define CP_WAIT1()  asm volatile("cp.async.wait_group 1;" ::: "memory")

__device__ __forceinline__ void split1(float x, bf16& h, bf16& l) {
    h = __float2bfloat16(x);
    l = __float2bfloat16(x - __bfloat162float(h));
}

// ---------------- prep ----------------
__global__ __launch_bounds__(192)
void adjprep_kernel(const float* __restrict__ adj) {
    int row = blockIdx.x;
    int t   = threadIdx.x;
    const float4 v = ((const float4*)(adj + (size_t)row * NDIM))[t];
    float s = v.x + v.y + v.z + v.w;
    __shared__ float ws[6];
    __shared__ float rsh;
#pragma unroll
    for (int o = 16; o > 0; o >>= 1) s += __shfl_down_sync(0xffffffffu, s, o);
    if ((t & 31) == 0) ws[t >> 5] = s;
    __syncthreads();
    if (t == 0) {
        float tot = ws[0] + ws[1] + ws[2] + ws[3] + ws[4] + ws[5];
        rsh = (tot == 0.f) ? 0.f : (1.f / tot);
    }
    __syncthreads();
    float r = rsh;
    size_t base = (size_t)row * NDIM + t * 4;
    ((__nv_bfloat162*)(g_Adj + base))[0] =
        __nv_bfloat162(__float2bfloat16(v.x * r), __float2bfloat16(v.y * r));
    ((__nv_bfloat162*)(g_Adj + base))[1] =
        __nv_bfloat162(__float2bfloat16(v.z * r), __float2bfloat16(v.w * r));
}

__global__ __launch_bounds__(256)
void splitx_kernel(const float* __restrict__ X) {
    size_t i = ((size_t)blockIdx.x * 256 + threadIdx.x) * 4;
    float4 v = *(const float4*)(X + i);
    bf16 h0, l0, h1, l1, h2, l2, h3, l3;
    split1(v.x, h0, l0); split1(v.y, h1, l1); split1(v.z, h2, l2); split1(v.w, h3, l3);
    ((__nv_bfloat162*)(g_Xhi + i))[0] = __nv_bfloat162(h0, h1);
    ((__nv_bfloat162*)(g_Xhi + i))[1] = __nv_bfloat162(h2, h3);
    ((__nv_bfloat162*)(g_Xlo + i))[0] = __nv_bfloat162(l0, l1);
    ((__nv_bfloat162*)(g_Xlo + i))[1] = __nv_bfloat162(l2, l3);
}

__global__ __launch_bounds__(256)
void splitw_kernel(const float* __restrict__ W_l, const float* __restrict__ W_l1) {
    size_t i = ((size_t)blockIdx.x * 256 + threadIdx.x) * 4;
    {
        float4 v = *(const float4*)(W_l + i);
        bf16 h0, l0, h1, l1, h2, l2, h3, l3;
        split1(v.x, h0, l0); split1(v.y, h1, l1); split1(v.z, h2, l2); split1(v.w, h3, l3);
        ((__nv_bfloat162*)(g_Wl_hi + i))[0] = __nv_bfloat162(h0, h1);
        ((__nv_bfloat162*)(g_Wl_hi + i))[1] = __nv_bfloat162(h2, h3);
        ((__nv_bfloat162*)(g_Wl_lo + i))[0] = __nv_bfloat162(l0, l1);
        ((__nv_bfloat162*)(g_Wl_lo + i))[1] = __nv_bfloat162(l2, l3);
    }
    {
        float4 v = *(const float4*)(W_l1 + i);
        ((__nv_bfloat162*)(g_Wl1_hi + i))[0] =
            __nv_bfloat162(__float2bfloat16(v.x), __float2bfloat16(v.y));
        ((__nv_bfloat162*)(g_Wl1_hi + i))[1] =
            __nv_bfloat162(__float2bfloat16(v.z), __float2bfloat16(v.w));
    }
}

// ---------------- gemm3: out = X @ W_l (3-term, fp32, 2-stage, 2 CTA/SM) ----------------
__global__ __launch_bounds__(256, 2)
void gemm3_kernel(float* __restrict__ out) {
    extern __shared__ char sm[];
    const uint32_t smb = smem_u32(sm);

    const int nb = blockIdx.x * 128;
    const int mb = blockIdx.y * 128;
    const int tid  = threadIdx.x;
    const int lane = tid & 31;
    const int wid  = tid >> 5;
    const int wm   = wid >> 1;
    const int wn   = wid & 1;
    const int ar  = tid >> 1;
    const int ak  = (tid & 1) * 16;
    const int bkr = tid >> 3;
    const int bn  = (tid & 7) * 16;

    auto issue = [&](int kt) {
        const uint32_t st = smb + (kt & 1) * S3_BYTES;
        const size_t asrc = (size_t)(mb + ar) * NDIM + kt * BK;
        const size_t bsrc = (size_t)(kt * BK + bkr) * NDIM + nb;
#pragma unroll
        for (int c = 0; c < 2; c++) {
            int ko = ak + c * 8;
            uint32_t da = st + (uint32_t)(ar * APAD + ko) * 2;
            cp16(da + S3_AHI, g_Xhi + asrc + ko);
            cp16(da + S3_ALO, g_Xlo + asrc + ko);
            int no = bn + c * 8;
            uint32_t db = st + (uint32_t)(bkr * BPAD + no) * 2;
            cp16(db + S3_BHI, g_Wl_hi + bsrc + no);
            cp16(db + S3_BLO, g_Wl_lo + bsrc + no);
        }
        CP_COMMIT();
    };

    float acc[2][8][4];
#pragma unroll
    for (int i = 0; i < 2; i++)
#pragma unroll
        for (int j = 0; j < 8; j++)
#pragma unroll
            for (int q = 0; q < 4; q++) acc[i][j][q] = 0.f;

    issue(0);

#pragma unroll 1
    for (int kt = 0; kt < NKT; kt++) {
        if (kt + 1 < NKT) issue(kt + 1); else CP_COMMIT();
        CP_WAIT1();
        __syncthreads();

        const uint32_t st = smb + (kt & 1) * S3_BYTES;
#pragma unroll
        for (int ks = 0; ks < 2; ks++) {
            const int k0 = ks * 16;
            const uint32_t aaddr = st + (uint32_t)((wm * 32 + (lane & 15)) * APAD
                                                   + k0 + (lane >> 4) * 8) * 2;
            const uint32_t baddr = st + (uint32_t)((k0 + (lane & 15)) * BPAD
                                                   + wn * 64 + (lane >> 4) * 8) * 2;
            uint32_t ahi[2][4];
#pragma unroll
            for (int m = 0; m < 2; m++)
                ldsm4(ahi[m], aaddr + S3_AHI + (uint32_t)(m * 16 * APAD) * 2);
            {
                uint32_t bhi[4][4];
#pragma unroll
                for (int p = 0; p < 4; p++)
                    ldsm4t(bhi[p], baddr + S3_BHI + (uint32_t)(p * 16) * 2);
#pragma unroll
                for (int m = 0; m < 2; m++)
#pragma unroll
                    for (int p = 0; p < 4; p++)
#pragma unroll
                        for (int h = 0; h < 2; h++)
                            hmma(acc[m][p * 2 + h], ahi[m], &bhi[p][h * 2]);
                {
                    uint32_t alo[2][4];
#pragma unroll
                    for (int m = 0; m < 2; m++)
                        ldsm4(alo[m], aaddr + S3_ALO + (uint32_t)(m * 16 * APAD) * 2);
#pragma unroll
                    for (int m = 0; m < 2; m++)
#pragma unroll
                        for (int p = 0; p < 4; p++)
#pragma unroll
                            for (int h = 0; h < 2; h++)
                                hmma(acc[m][p * 2 + h], alo[m], &bhi[p][h * 2]);
                }
            }
            {
                uint32_t blo[4][4];
#pragma unroll
                for (int p = 0; p < 4; p++)
                    ldsm4t(blo[p], baddr + S3_BLO + (uint32_t)(p * 16) * 2);
#pragma unroll
                for (int m = 0; m < 2; m++)
#pragma unroll
                    for (int p = 0; p < 4; p++)
#pragma unroll
                        for (int h = 0; h < 2; h++)
                            hmma(acc[m][p * 2 + h], ahi[m], &blo[p][h * 2]);
            }
        }
        __syncthreads();
    }

    const int row0 = mb + wm * 32 + (lane >> 2);
    const int col0 = nb + wn * 64 + (lane & 3) * 2;
#pragma unroll
    for (int m = 0; m < 2; m++)
#pragma unroll
        for (int ns = 0; ns < 8; ns++) {
            float* c0 = out + (size_t)(row0 + m * 16) * NDIM + col0 + ns * 8;
            float* c1 = c0 + 8 * NDIM;
            *(float2*)c0 = make_float2(acc[m][ns][0], acc[m][ns][1]);
            *(float2*)c1 = make_float2(acc[m][ns][2], acc[m][ns][3]);
        }
}

// ---------------- 1-term body (3-stage). EPI=0: bf16 store; EPI=1: lrelu RMW ----------------
template<int EPI>
__device__ __forceinline__ void gemm1t_body(
    const bf16* __restrict__ A, const bf16* __restrict__ B,
    float* __restrict__ outF, bf16* __restrict__ outH,
    int mb, int nb)
{
    extern __shared__ char sm[];
    const uint32_t smb = smem_u32(sm);

    const int tid  = threadIdx.x;
    const int lane = tid & 31;
    const int wid  = tid >> 5;
    const int wm   = wid >> 1;
    const int wn   = wid & 1;
    const int ar  = tid >> 1;
    const int ak  = (tid & 1) * 16;
    const int bkr = tid >> 3;
    const int bn  = (tid & 7) * 16;

    auto issue = [&](int kt) {
        const uint32_t st = smb + (kt % 3) * S1_BYTES;
        const size_t asrc = (size_t)(mb + ar) * NDIM + kt * BK;
        const size_t bsrc = (size_t)(kt * BK + bkr) * NDIM + nb;
#pragma unroll
        for (int c = 0; c < 2; c++) {
            int ko = ak + c * 8;
            cp16(st + S1_AHI + (uint32_t)(ar * APAD + ko) * 2, A + asrc + ko);
            int no = bn + c * 8;
            cp16(st + S1_BHI + (uint32_t)(bkr * BPAD + no) * 2, B + bsrc + no);
        }
        CP_COMMIT();
    };

    float acc[2][8][4];
#pragma unroll
    for (int i = 0; i < 2; i++)
#pragma unroll
        for (int j = 0; j < 8; j++)
#pragma unroll
            for (int q = 0; q < 4; q++) acc[i][j][q] = 0.f;

    issue(0);
    issue(1);

#pragma unroll 1
    for (int kt = 0; kt < NKT; kt++) {
        CP_WAIT1();
        __syncthreads();
        if (kt + 2 < NKT) issue(kt + 2); else CP_COMMIT();

        const uint32_t st = smb + (kt % 3) * S1_BYTES;
#pragma unroll
        for (int ks = 0; ks < 2; ks++) {
            const int k0 = ks * 16;
            uint32_t ahi[2][4], bhi[4][4];
#pragma unroll
            for (int m = 0; m < 2; m++)
                ldsm4(ahi[m], st + S1_AHI + (uint32_t)((wm * 32 + m * 16 + (lane & 15)) * APAD
                                                       + k0 + (lane >> 4) * 8) * 2);
#pragma unroll
            for (int p = 0; p < 4; p++)
                ldsm4t(bhi[p], st + S1_BHI + (uint32_t)((k0 + (lane & 15)) * BPAD
                                                        + wn * 64 + p * 16 + (lane >> 4) * 8) * 2);
#pragma unroll
            for (int m = 0; m < 2; m++)
#pragma unroll
                for (int p = 0; p < 4; p++)
#pragma unroll
                    for (int h = 0; h < 2; h++)
                        hmma(acc[m][p * 2 + h], ahi[m], &bhi[p][h * 2]);
        }
    }

    const int row0 = mb + wm * 32 + (lane >> 2);
    const int col0 = nb + wn * 64 + (lane & 3) * 2;
    if (EPI == 0) {
#pragma unroll
        for (int m = 0; m < 2; m++)
#pragma unroll
            for (int ns = 0; ns < 8; ns++) {
                bf16* c0 = outH + (size_t)(row0 + m * 16) * NDIM + col0 + ns * 8;
                bf16* c1 = c0 + 8 * NDIM;
                *(__nv_bfloat162*)c0 = __nv_bfloat162(
                    __float2bfloat16(acc[m][ns][0]), __float2bfloat16(acc[m][ns][1]));
                *(__nv_bfloat162*)c1 = __nv_bfloat162(
                    __float2bfloat16(acc[m][ns][2]), __float2bfloat16(acc[m][ns][3]));
            }
    } else {
#pragma unroll
        for (int m = 0; m < 2; m++)
#pragma unroll
            for (int ns = 0; ns < 8; ns++) {
                float* c0 = outF + (size_t)(row0 + m * 16) * NDIM + col0 + ns * 8;
                float* c1 = c0 + 8 * NDIM;
                float2 x0 = *(float2*)c0;
                float2 x1 = *(float2*)c1;
                float h0 = acc[m][ns][0] + x0.x;
                float h1 = acc[m][ns][1] + x0.y;
                float h2 = acc[m][ns][2] + x1.x;
                float h3 = acc[m][ns][3] + x1.y;
                h0 = (h0 > 0.f) ? h0 : 0.01f * h0;
                h1 = (h1 > 0.f) ? h1 : 0.01f * h1;
                h2 = (h2 > 0.f) ? h2 : 0.01f * h2;
                h3 = (h3 > 0.f) ? h3 : 0.01f * h3;
                *(float2*)c0 = make_float2(h0, h1);
                *(float2*)c1 = make_float2(h2, h3);
            }
    }
}

// Y = adj_n @ Xhi  (per batch), runs on side stream
__global__ __launch_bounds__(256, 2)
void aggx_kernel() {
    const size_t bo = (size_t)blockIdx.z * NDIM * NDIM;
    gemm1t_body<0>(g_Adj + bo, g_Xhi + bo, nullptr, g_Y + bo,
                   blockIdx.y * 128, blockIdx.x * 128);
}

// out = lrelu(out + Y @ Wl1hi)  (flat over all rows)
__global__ __launch_bounds__(256, 2)
void final_kernel(float* __restrict__ out) {
    gemm1t_body<1>(g_Y, g_Wl1_hi, out, nullptr, blockIdx.y * 128, blockIdx.x * 128);
}

// ---------------------------------------------------------------------------
extern "C" void kernel_launch(void* const* d_in, const int* in_sizes, int n_in,
                              void* d_out, int out_size)
{
    const float* X    = (const float*)d_in[0];
    const float* adj  = (const float*)d_in[1];
    const float* W_l  = (const float*)d_in[2];
    const float* W_l1 = (const float*)d_in[3];
    float* out = (float*)d_out;

    static cudaStream_t s1 = nullptr;
    static cudaEvent_t ev0 = nullptr, ev1 = nullptr;
    if (!s1) {
        cudaStreamCreateWithFlags(&s1, cudaStreamNonBlocking);
        cudaEventCreateWithFlags(&ev0, cudaEventDisableTiming);
        cudaEventCreateWithFlags(&ev1, cudaEventDisableTiming);
        cudaFuncSetAttribute(gemm3_kernel, cudaFuncAttributeMaxDynamicSharedMemorySize, SMEM3);
        cudaFuncSetAttribute(aggx_kernel,  cudaFuncAttributeMaxDynamicSharedMemorySize, SMEM1T);
        cudaFuncSetAttribute(final_kernel, cudaFuncAttributeMaxDynamicSharedMemorySize, SMEM1T);
    }

    // prep (main stream)
    adjprep_kernel<<<MTOT, 192>>>(adj);
    splitx_kernel<<<(MTOT * NDIM) / 1024, 256>>>(X);
    splitw_kernel<<<(NDIM * NDIM) / 1024, 256>>>(W_l, W_l1);

    // fork: aggx on s1, concurrent with gemm3 on main stream
    cudaEventRecord(ev0, 0);
    cudaStreamWaitEvent(s1, ev0, 0);
    aggx_kernel<<<dim3(6, 6, 32), 256, SMEM1T, s1>>>();
    cudaEventRecord(ev1, s1);

    gemm3_kernel<<<dim3(6, 192), 256, SMEM3>>>(out);

    // join, then final
    cudaStreamWaitEvent(0, ev1, 0);
    final_kernel<<<dim3(6, 192), 256, SMEM1T>>>(out);
}